// round 8
// baseline (speedup 1.0000x reference)
#include <cuda_runtime.h>
#include <cuda_fp16.h>
#include <cstdint>

#define EMB_DIM 300
#define KP      304                 // K padded to multiple of 16
#define NTOT    2048
#define MTOT    32768
#define MTILE   128
#define NCHUNK  128
#define NCHUNKS (NTOT / NCHUNK)     // 16
#define ASTR    312                 // halves per A row (conflict-free ldmatrix)
#define BSTR    136                 // halves per B row (conflict-free ldmatrix)
#define KH0R    160                 // k-rows in half 0 (ksteps 0..9)
#define KH1R    144                 // k-rows in half 1 (ksteps 10..18)
#define KS0     10
#define KS1     9
#define A_BYTES (MTILE * ASTR * 2)  // 79872
#define BBUF    (KH0R * BSTR * 2)   // 43520 (buffer sized for the larger half)
#define SMEM_BYTES (A_BYTES + 2 * BBUF)   // 166912
#define SCALE 45.254833995939045f   // sqrt(2048)

__device__ __half g_Wh[KP * NTOT];  // fp16 W, K zero-padded
__device__ float  g_bs[NTOT];       // bias * scale

__global__ void prep(const float* __restrict__ W, const float* __restrict__ b) {
    int i = blockIdx.x * blockDim.x + threadIdx.x;
    if (i < KP * NTOT) {
        int k = i / NTOT, n = i % NTOT;
        g_Wh[i] = __float2half_rn((k < EMB_DIM) ? W[k * NTOT + n] : 0.0f);
    }
    if (i < NTOT) g_bs[i] = b[i] * SCALE;
}

__device__ __forceinline__ void ldm_x4(uint32_t* r, uint32_t a) {
    asm volatile("ldmatrix.sync.aligned.m8n8.x4.shared.b16 {%0,%1,%2,%3}, [%4];"
                 : "=r"(r[0]), "=r"(r[1]), "=r"(r[2]), "=r"(r[3]) : "r"(a));
}
__device__ __forceinline__ void ldm_x4_t(uint32_t* r, uint32_t a) {
    asm volatile("ldmatrix.sync.aligned.m8n8.x4.trans.shared.b16 {%0,%1,%2,%3}, [%4];"
                 : "=r"(r[0]), "=r"(r[1]), "=r"(r[2]), "=r"(r[3]) : "r"(a));
}
__device__ __forceinline__ void mma16816(float* d, const uint32_t* a, const uint32_t* b) {
    asm volatile("mma.sync.aligned.m16n8k16.row.col.f32.f16.f16.f32 "
                 "{%0,%1,%2,%3}, {%4,%5,%6,%7}, {%8,%9}, {%0,%1,%2,%3};"
                 : "+f"(d[0]), "+f"(d[1]), "+f"(d[2]), "+f"(d[3])
                 : "r"(a[0]), "r"(a[1]), "r"(a[2]), "r"(a[3]),
                   "r"(b[0]), "r"(b[1]));
}

// cp.async one K-half of a B chunk: rows [kr0, kr0+nrows) x cols [n0, n0+128)
__device__ __forceinline__ void cp_bhalf(uint32_t dstU, int n0, int kr0,
                                         int nrows, int tid) {
    int tot = nrows * 16;                       // uint4 per half
    for (int i = tid; i < tot; i += 256) {
        int r = i >> 4, j = i & 15;
        uint32_t dst = dstU + (uint32_t)r * (BSTR * 2) + (uint32_t)j * 16;
        size_t g = __cvta_generic_to_global(g_Wh + (size_t)(kr0 + r) * NTOT
                                            + n0 + 8 * j);
        asm volatile("cp.async.cg.shared.global [%0], [%1], 16;"
                     :: "r"(dst), "l"(g));
    }
}

// one MMA phase over NSTEPS k-steps, frag double-buffered
template <int NSTEPS>
__device__ __forceinline__ void mma_phase(uint32_t aBase, uint32_t bBase,
                                          float (&acc)[4][4][4]) {
    uint32_t af[2][4][4], bf[2][2][4];
    #pragma unroll
    for (int mt = 0; mt < 4; ++mt)
        ldm_x4(af[0][mt], aBase + (uint32_t)(mt * 16 * ASTR) * 2);
    #pragma unroll
    for (int p = 0; p < 2; ++p)
        ldm_x4_t(bf[0][p], bBase + (uint32_t)p * 32);

    #pragma unroll
    for (int ks = 0; ks < NSTEPS; ++ks) {
        int cur = ks & 1, nxt = cur ^ 1;
        if (ks + 1 < NSTEPS) {
            uint32_t kbA = (uint32_t)(ks + 1) * 32;
            uint32_t kbB = (uint32_t)(ks + 1) * 16 * (BSTR * 2);
            #pragma unroll
            for (int mt = 0; mt < 4; ++mt)
                ldm_x4(af[nxt][mt], aBase + (uint32_t)(mt * 16 * ASTR) * 2 + kbA);
            #pragma unroll
            for (int p = 0; p < 2; ++p)
                ldm_x4_t(bf[nxt][p], bBase + (uint32_t)p * 32 + kbB);
        }
        #pragma unroll
        for (int mt = 0; mt < 4; ++mt)
            #pragma unroll
            for (int nt = 0; nt < 4; ++nt) {
                uint32_t bb[2] = { bf[cur][nt >> 1][(nt & 1) * 2],
                                   bf[cur][nt >> 1][(nt & 1) * 2 + 1] };
                mma16816(acc[mt][nt], af[cur][mt], bb);
            }
    }
}

__global__ __launch_bounds__(256, 1)
void gemm_kernel(const int* __restrict__ x, const float* __restrict__ emb,
                 float* __restrict__ out) {
    extern __shared__ __half sm[];
    __half* A_s = sm;                          // [MTILE][ASTR]
    const uint32_t smem_u = (uint32_t)__cvta_generic_to_shared(sm);
    const uint32_t bBuf0  = smem_u + A_BYTES;
    const uint32_t bBuf1  = bBuf0 + BBUF;

    const int tid = threadIdx.x;
    const int m0  = blockIdx.x * MTILE;

    // prologue: both halves of chunk 0 in flight, then A gather overlaps
    cp_bhalf(bBuf0, 0, 0, KH0R, tid);
    asm volatile("cp.async.commit_group;" ::: "memory");
    cp_bhalf(bBuf1, 0, KH0R, KH1R, tid);
    asm volatile("cp.async.commit_group;" ::: "memory");

    // ---- Gather A: 128 rows, 2 threads/row, fp32 -> fp16 ----
    {
        int r = tid >> 1;
        int token = x[m0 + r];
        const float4* src = (const float4*)(emb + (size_t)token * EMB_DIM);
        __half* dstrow = A_s + r * ASTR;
        #pragma unroll
        for (int j = (tid & 1); j < 75; j += 2) {   // 75 float4 per row
            float4 v = src[j];
            __half2* d2 = (__half2*)(dstrow + 4 * j);
            d2[0] = __floats2half2_rn(v.x, v.y);
            d2[1] = __floats2half2_rn(v.z, v.w);
        }
        if (tid < MTILE) {                      // zero K pad 300..303
            __half2* zp = (__half2*)(A_s + tid * ASTR + 300);
            zp[0] = __half2half2(__float2half(0.0f));
            zp[1] = __half2half2(__float2half(0.0f));
        }
    }

    const int lane = tid & 31, wid = tid >> 5;   // 8 warps
    const int wm = wid & 1;         // 0..1 : m64 each
    const int wn = wid >> 1;        // 0..3 : n32 each
    const int bq = lane >> 3, rq = lane & 7;

    const uint32_t aBase0 = smem_u
        + (uint32_t)((wm * 64 + (bq & 1) * 8 + rq) * ASTR) * 2
        + (uint32_t)(bq >> 1) * 16;
    const uint32_t aBase1 = aBase0 + (uint32_t)KS0 * 32;   // ksteps 10.. in A
    const uint32_t bLane = (uint32_t)(((bq & 1) * 8 + rq) * BSTR) * 2
                         + (uint32_t)(wn * 64 + (bq >> 1) * 16);

    #pragma unroll 1
    for (int nc = 0; nc < NCHUNKS; ++nc) {
        float acc[4][4][4];
        #pragma unroll
        for (int mt = 0; mt < 4; ++mt)
            #pragma unroll
            for (int nt = 0; nt < 4; ++nt)
                #pragma unroll
                for (int q = 0; q < 4; ++q) acc[mt][nt][q] = 0.0f;

        int n0n = (nc + 1) * NCHUNK;

        // ---- phase 0: buf0 ready? ----
        asm volatile("cp.async.wait_group 1;" ::: "memory");
        __syncthreads();
        mma_phase<KS0>(aBase0, bBuf0 + bLane, acc);
        __syncthreads();                         // all warps done with buf0
        if (n0n < NTOT) cp_bhalf(bBuf0, n0n, 0, KH0R, tid);
        asm volatile("cp.async.commit_group;" ::: "memory");

        // ---- phase 1: buf1 ready? ----
        asm volatile("cp.async.wait_group 1;" ::: "memory");
        __syncthreads();
        mma_phase<KS1>(aBase1, bBuf1 + bLane, acc);
        __syncthreads();                         // all warps done with buf1
        if (n0n < NTOT) cp_bhalf(bBuf1, n0n, KH0R, KH1R, tid);
        asm volatile("cp.async.commit_group;" ::: "memory");

        // ---- epilogue (covers in-flight loads of chunk nc+1) ----
        int n0 = nc * NCHUNK;
        #pragma unroll
        for (int nt = 0; nt < 4; ++nt) {
            int col = n0 + wn * 32 + nt * 8 + (lane & 3) * 2;
            float2 cb = *(const float2*)(g_bs + col);
            #pragma unroll
            for (int mt = 0; mt < 4; ++mt) {
                int row = m0 + wm * 64 + mt * 16 + (lane >> 2);
                float2 v0 = { fmaf(acc[mt][nt][0], SCALE, cb.x),
                              fmaf(acc[mt][nt][1], SCALE, cb.y) };
                float2 v1 = { fmaf(acc[mt][nt][2], SCALE, cb.x),
                              fmaf(acc[mt][nt][3], SCALE, cb.y) };
                *(float2*)(out + (size_t)row * NTOT + col)       = v0;
                *(float2*)(out + (size_t)(row + 8) * NTOT + col) = v1;
            }
        }
    }
}

extern "C" void kernel_launch(void* const* d_in, const int* in_sizes, int n_in,
                              void* d_out, int out_size) {
    const int*   x    = (const int*)  d_in[0];
    const float* emb  = (const float*)d_in[1];
    const float* W    = (const float*)d_in[2];
    const float* bias = (const float*)d_in[3];
    float*       out  = (float*)      d_out;

    cudaFuncSetAttribute(gemm_kernel, cudaFuncAttributeMaxDynamicSharedMemorySize,
                         SMEM_BYTES);

    prep<<<(KP * NTOT + 255) / 256, 256>>>(W, bias);
    gemm_kernel<<<MTOT / MTILE, 256, SMEM_BYTES>>>(x, emb, out);
}